// round 13
// baseline (speedup 1.0000x reference)
#include <cuda_runtime.h>
#include <math.h>

// Problem constants (fixed by the dataset)
#define Bq 2
#define Lq 32
#define Eq 256
#define Hq 4096
#define Gq 16
#define Rq 64
#define H4 1024      // Hq/4 (float4 units)
#define HSPAN 512    // h-floats per fused block
#define HSPAN4 128   // f4 per fused block
#define NCH 16       // 32-float chunks per h-span

// Scratch (device globals; no allocation in kernel_launch)
__device__ float g_wall[17*Hq];        // row0 = Wk^T@lq, rows 1..16 = 0.125*q@Wk
__device__ float g_lscore[Bq*Lq];      // layer scores (accum)      [B,L]
__device__ float g_q[Gq*Rq];           // global_q @ Wq^T           [G,R]
__device__ float g_ps[Bq*Lq*Gq*Eq];    // per-layer score partials  [B,L,G,E] 1MB (accum)
__device__ float g_aw[Bq*Eq];          // mean_g attn               [B,E]
__device__ float g_sh[Bq*Hq];          // Σ_{l,e} c*evv (accum)     [B,H]
__device__ float g_snew[Bq*Rq];        // projected new state       [B,R]
__device__ unsigned int g_ctr;         // last-block counter for fused fin

// ---- packed f32x2 helpers --------------------------------------------------
__device__ __forceinline__ unsigned long long pk2(float a, float b) {
    unsigned long long r;
    asm("mov.b64 %0, {%1, %2};" : "=l"(r) : "f"(a), "f"(b));
    return r;
}
__device__ __forceinline__ void fma2(unsigned long long& d,
                                     unsigned long long a, unsigned long long b) {
    asm("fma.rn.f32x2 %0, %1, %2, %0;" : "+l"(d) : "l"(a), "l"(b));
}
__device__ __forceinline__ float hsum2(unsigned long long v) {
    float x, y;
    asm("mov.b64 {%0, %1}, %2;" : "=f"(x), "=f"(y) : "l"(v));
    return x + y;
}

// ---------------------------------------------------------------------------
// K1: blocks 0..15  : g_wall[0][h] = Σ_r Wk[r,h]*lq[r]
//     block  16     : zero accumulators + counter
//     blocks 17..80 : q[g,r] = Σ_h gq[g,h]*Wq[r,h]  (one block per r)
// grid(81) x 256
__global__ void k_prep(const float* __restrict__ Wk, const float* __restrict__ lq,
                       const float4* __restrict__ gq4, const float4* __restrict__ wq4) {
    int tid = threadIdx.x;
    int bx = blockIdx.x;
    if (bx < 16) {
        __shared__ float slq[Rq];
        if (tid < Rq) slq[tid] = lq[tid];
        __syncthreads();
        int h = bx * 256 + tid;
        float s = 0.f;
        #pragma unroll
        for (int r = 0; r < Rq; ++r) s += Wk[r * Hq + h] * slq[r];
        g_wall[h] = s;
    } else if (bx == 16) {
        if (tid < Bq * Lq) g_lscore[tid] = 0.f;
        for (int i = tid; i < Bq * Hq; i += 256) g_sh[i] = 0.f;
        if (tid == 0) g_ctr = 0u;
    } else {
        int r = bx - 17;                       // 0..63
        float4 w[4];
        #pragma unroll
        for (int j = 0; j < 4; ++j) w[j] = wq4[r * H4 + j * 256 + tid];
        float p[Gq];
        #pragma unroll
        for (int g = 0; g < Gq; ++g) {
            float s = 0.f;
            #pragma unroll
            for (int j = 0; j < 4; ++j) {
                float4 a = gq4[g * H4 + j * 256 + tid];
                s += a.x * w[j].x + a.y * w[j].y + a.z * w[j].z + a.w * w[j].w;
            }
            p[g] = s;
        }
        __shared__ float sbuf[Gq * 8];
        int lane = tid & 31, warp = tid >> 5;
        #pragma unroll
        for (int g = 0; g < Gq; ++g) {
            float v = p[g];
            #pragma unroll
            for (int o = 16; o; o >>= 1) v += __shfl_down_sync(0xffffffffu, v, o);
            if (lane == 0) sbuf[g * 8 + warp] = v;
        }
        __syncthreads();
        if (tid < Gq) {
            float s = 0.f;
            #pragma unroll
            for (int wgt = 0; wgt < 8; ++wgt) s += sbuf[tid * 8 + wgt];
            g_q[tid * Rq + r] = s;
        }
    }
}

// ---------------------------------------------------------------------------
// K2: g_wall[1+g][h] = 0.125 * Σ_r q[g,r]*Wk[r,h]; also zeroes g_ps.
// grid(4 hc, 16 g) x 256
__global__ void k_qkh(const float4* __restrict__ wk4) {
    int tid = threadIdx.x;
    int hc = blockIdx.x, g = blockIdx.y;
    // zero a 1024-f4 slice of g_ps (64 blocks x 1024 f4 = 1MB)
    float4* ps4 = (float4*)g_ps;
    int zbase = (g * 4 + hc) * 1024;
    #pragma unroll
    for (int i = 0; i < 4; ++i)
        ps4[zbase + i * 256 + tid] = make_float4(0.f, 0.f, 0.f, 0.f);
    __shared__ float sq[Rq];
    if (tid < Rq) sq[tid] = g_q[g * Rq + tid];
    __syncthreads();
    int h4 = hc * 256 + tid;
    float4 v = make_float4(0.f, 0.f, 0.f, 0.f);
    #pragma unroll 16
    for (int r = 0; r < Rq; ++r) {
        float4 w = wk4[r * H4 + h4];
        float qv = sq[r];
        v.x += qv * w.x; v.y += qv * w.y; v.z += qv * w.z; v.w += qv * w.w;
    }
    v.x *= 0.125f; v.y *= 0.125f; v.z *= 0.125f; v.w *= 0.125f;  // inv_sqrt_r
    ((float4*)g_wall)[(1 + g) * H4 + h4] = v;
}

// ---------------------------------------------------------------------------
// K3: SINGLE fused pass over evicted_k (268 MB, read ONCE):
//   lscore[b,l]      += Σ_{e,h} evk * wall[0]
//   pscore[b,l,g,e]  += Σ_h     evk * wall[1+g]   (partial over this block's h-span)
// grid(16 = hs*2+et, L, B) x 256.  Thread: eg=tid>>2 owns 2 e-rows, hp=tid&3 owns
// a 64B+64B slice of each 128B chunk-row. Weights via LDS.64 broadcast, packed FFMA2.
__global__ __launch_bounds__(256, 2) void k_fused(const float4* __restrict__ evk4) {
    __shared__ float ws[17 * HSPAN];   // 34816 B
    int tid = threadIdx.x;
    int hs = blockIdx.x >> 1, et = blockIdx.x & 1;
    int l = blockIdx.y, b = blockIdx.z;
    // stage the W slice [17][HSPAN]
    {
        const float4* wall4 = (const float4*)g_wall;
        float4* ws4 = (float4*)ws;
        for (int i = tid; i < 17 * HSPAN4; i += 256) {
            int r = i >> 7, c = i & (HSPAN4 - 1);
            ws4[i] = wall4[r * H4 + hs * HSPAN4 + c];
        }
    }
    __syncthreads();
    int eg = tid >> 2, hp = tid & 3;
    int e0 = et * 128 + eg * 2;
    const float4* row0 = evk4 + ((size_t)((b * Lq + l) * Eq + e0)) * H4 + hs * HSPAN4;

    unsigned long long acc[2][17];
    #pragma unroll
    for (int r = 0; r < 2; ++r)
        #pragma unroll
        for (int g = 0; g < 17; ++g) acc[r][g] = 0ULL;

    for (int c = 0; c < NCH; ++c) {
        float4 d[2][2];
        #pragma unroll
        for (int r = 0; r < 2; ++r) {
            d[r][0] = row0[(size_t)r * H4 + c * 8 + hp];        // f4 hp   (64B group)
            d[r][1] = row0[(size_t)r * H4 + c * 8 + 4 + hp];    // f4 hp+4
        }
        #pragma unroll
        for (int k = 0; k < 2; ++k) {
            int wo = c * 32 + k * 16 + hp * 4;                  // float offset in span
            unsigned long long a0lo = pk2(d[0][k].x, d[0][k].y);
            unsigned long long a0hi = pk2(d[0][k].z, d[0][k].w);
            unsigned long long a1lo = pk2(d[1][k].x, d[1][k].y);
            unsigned long long a1hi = pk2(d[1][k].z, d[1][k].w);
            #pragma unroll
            for (int g = 0; g < 17; ++g) {
                float2 wlo = *(const float2*)&ws[g * HSPAN + wo];
                float2 whi = *(const float2*)&ws[g * HSPAN + wo + 2];
                unsigned long long w2lo = pk2(wlo.x, wlo.y);
                unsigned long long w2hi = pk2(whi.x, whi.y);
                fma2(acc[0][g], a0lo, w2lo);
                fma2(acc[0][g], a0hi, w2hi);
                fma2(acc[1][g], a1lo, w2lo);
                fma2(acc[1][g], a1hi, w2hi);
            }
        }
    }
    // reduce across the hp quad (lanes xor 1, 2)
    float lsum = 0.f;
    #pragma unroll
    for (int r = 0; r < 2; ++r) {
        float v[17];
        #pragma unroll
        for (int g = 0; g < 17; ++g) {
            float t = hsum2(acc[r][g]);
            t += __shfl_xor_sync(0xffffffffu, t, 1);
            t += __shfl_xor_sync(0xffffffffu, t, 2);
            v[g] = t;
        }
        if (hp == 0) {
            lsum += v[0];
            int e = e0 + r;
            #pragma unroll
            for (int g = 0; g < Gq; ++g)
                atomicAdd(&g_ps[((b * Lq + l) * Gq + g) * Eq + e], v[g + 1]);
        }
    }
    // lscore: block reduce of hp==0 contributions, one atomic per block
    float t = (hp == 0) ? lsum : 0.f;
    #pragma unroll
    for (int o = 16; o; o >>= 1) t += __shfl_xor_sync(0xffffffffu, t, o);
    __shared__ float sred[8];
    int lane = tid & 31, warp = tid >> 5;
    if (lane == 0) sred[warp] = t;
    __syncthreads();
    if (tid == 0) {
        float s = 0.f;
        #pragma unroll
        for (int w = 0; w < 8; ++w) s += sred[w];
        atomicAdd(&g_lscore[b * Lq + l], s);
    }
}

// ---------------------------------------------------------------------------
// K4: lw softmax; scores[g,e] = Σ_l lw*ps; softmax over e per g; aw = mean_g.
// grid(B) x 512 (one warp per g). All data L2-resident (~1MB).
__global__ void k_comb() {
    int tid = threadIdx.x;
    int b = blockIdx.x;
    int lane = tid & 31, g = tid >> 5;
    __shared__ float slw[Lq];
    __shared__ float sbuf[Gq * Eq];     // 16KB
    if (tid < 32) {
        float s = g_lscore[b * Lq + tid] * (1.0f / 2048.0f);  // inv_sqrt_r/(temp*E)
        float m = s;
        #pragma unroll
        for (int o = 16; o; o >>= 1) m = fmaxf(m, __shfl_xor_sync(0xffffffffu, m, o));
        float ex = expf(s - m);
        float sum = ex;
        #pragma unroll
        for (int o = 16; o; o >>= 1) sum += __shfl_xor_sync(0xffffffffu, sum, o);
        slw[tid] = ex / sum;
    }
    __syncthreads();
    float s[8];
    #pragma unroll
    for (int j = 0; j < 8; ++j) s[j] = 0.f;
    for (int l = 0; l < Lq; ++l) {
        float w = slw[l];
        const float* p = &g_ps[((b * Lq + l) * Gq + g) * Eq];
        #pragma unroll
        for (int j = 0; j < 8; ++j) s[j] += w * p[j * 32 + lane];
    }
    float m = -1e30f;
    #pragma unroll
    for (int j = 0; j < 8; ++j) m = fmaxf(m, s[j]);
    #pragma unroll
    for (int o = 16; o; o >>= 1) m = fmaxf(m, __shfl_xor_sync(0xffffffffu, m, o));
    float sum = 0.f;
    #pragma unroll
    for (int j = 0; j < 8; ++j) { s[j] = expf(s[j] - m); sum += s[j]; }
    #pragma unroll
    for (int o = 16; o; o >>= 1) sum += __shfl_xor_sync(0xffffffffu, sum, o);
    float inv = 1.0f / sum;
    #pragma unroll
    for (int j = 0; j < 8; ++j) sbuf[g * Eq + j * 32 + lane] = s[j] * inv;
    __syncthreads();
    if (tid < Eq) {
        float a = 0.f;
        #pragma unroll
        for (int gg = 0; gg < Gq; ++gg) a += sbuf[gg * Eq + tid];
        g_aw[b * Eq + tid] = a * (1.0f / (float)Gq);
    }
}

// ---------------------------------------------------------------------------
// K5: sh[b,h] += Σ_{l,e} (lw[b,l]*aw[b,e]) * evv[b,l,e,h]  (268 MB, read ONCE)
// grid(4 hc, L, B*2 e-halves) x 256; inline lw softmax.
__global__ void k_sh2(const float4* __restrict__ evv4) {
    __shared__ float sca[128];
    __shared__ float slw_s;
    int tid = threadIdx.x;
    int hc = blockIdx.x, l = blockIdx.y;
    int b = blockIdx.z & 1, eh = blockIdx.z >> 1;
    if (tid < 32) {
        float s = g_lscore[b * Lq + tid] * (1.0f / 2048.0f);
        float m = s;
        #pragma unroll
        for (int o = 16; o; o >>= 1) m = fmaxf(m, __shfl_xor_sync(0xffffffffu, m, o));
        float ex = expf(s - m);
        float sum = ex;
        #pragma unroll
        for (int o = 16; o; o >>= 1) sum += __shfl_xor_sync(0xffffffffu, sum, o);
        if (tid == l) slw_s = ex / sum;
    }
    __syncthreads();
    if (tid < 128) sca[tid] = g_aw[b * Eq + eh * 128 + tid] * slw_s;
    __syncthreads();
    const float4* base = evv4 + ((size_t)((b * Lq + l) * Eq + eh * 128)) * H4
                       + hc * 256 + tid;
    float4 acc = make_float4(0.f, 0.f, 0.f, 0.f);
    #pragma unroll 4
    for (int e = 0; e < 128; ++e) {
        float4 d = base[(size_t)e * H4];
        float c = sca[e];
        acc.x += c * d.x; acc.y += c * d.y; acc.z += c * d.z; acc.w += c * d.w;
    }
    float* shp = &g_sh[b * Hq + (hc * 256 + tid) * 4];
    atomicAdd(shp + 0, acc.x);
    atomicAdd(shp + 1, acc.y);
    atomicAdd(shp + 2, acc.z);
    atomicAdd(shp + 3, acc.w);
}

// ---------------------------------------------------------------------------
// K6: s_new[b,r] = Σ_h sh[b,h]*Wv[r,h] (one block per r); LAST block does the
// gated update + norm clamp.  grid(64) x 256.
__global__ void k_snew_fin(const float4* __restrict__ wv4,
                           const float* __restrict__ state,
                           const int* __restrict__ tok,
                           float* __restrict__ out) {
    int tid = threadIdx.x;
    int r = blockIdx.x;
    const float4* sh4 = (const float4*)g_sh;
    float4 w[4];
    #pragma unroll
    for (int j = 0; j < 4; ++j) w[j] = wv4[r * H4 + j * 256 + tid];
    float p[Bq];
    #pragma unroll
    for (int b = 0; b < Bq; ++b) {
        float s = 0.f;
        #pragma unroll
        for (int j = 0; j < 4; ++j) {
            float4 a = sh4[b * H4 + j * 256 + tid];
            s += a.x * w[j].x + a.y * w[j].y + a.z * w[j].z + a.w * w[j].w;
        }
        p[b] = s;
    }
    __shared__ float sbuf[Bq * 8];
    int lane = tid & 31, warp = tid >> 5;
    #pragma unroll
    for (int b = 0; b < Bq; ++b) {
        float v = p[b];
        #pragma unroll
        for (int o = 16; o; o >>= 1) v += __shfl_down_sync(0xffffffffu, v, o);
        if (lane == 0) sbuf[b * 8 + warp] = v;
    }
    __syncthreads();
    if (tid < Bq) {
        float s = 0.f;
        #pragma unroll
        for (int wgt = 0; wgt < 8; ++wgt) s += sbuf[tid * 8 + wgt];
        g_snew[tid * Rq + r] = s;
    }
    __syncthreads();
    __shared__ int is_last;
    if (tid == 0) {
        __threadfence();
        is_last = (atomicAdd(&g_ctr, 1u) == (unsigned)(Rq - 1)) ? 1 : 0;
    }
    __syncthreads();
    if (!is_last) return;
    __threadfence();

    __shared__ float red[3 * 128];
    __shared__ float gate_s[Bq], scale_s[Bq];
    float pv = 0.f, sn = 0.f;
    if (tid < 128) {
        pv = state[tid];
        sn = g_snew[tid];
        red[tid] = pv * pv; red[128 + tid] = sn * sn; red[256 + tid] = pv * sn;
    }
    __syncthreads();
    if (tid < Bq) {
        float pp = 0.f, ss = 0.f, ps = 0.f;
        int base = tid * 64;
        for (int i = 0; i < 64; ++i) {
            pp += red[base + i]; ss += red[128 + base + i]; ps += red[256 + base + i];
        }
        float np = fmaxf(sqrtf(pp), 1e-6f);
        float ns = fmaxf(sqrtf(ss), 1e-6f);
        float sim = ps / (np * ns);
        sim = fminf(1.f, fmaxf(-1.f, sim));
        float gate = 0.1f + 0.8f * 0.5f * (sim + 1.f);
        float evd = fminf(1.f, (float)tok[0] * (1.0f / 256.0f));
        gate_s[tid] = gate * evd;
    }
    __syncthreads();
    float u = 0.f;
    if (tid < 128) {
        float g = gate_s[tid >> 6];
        u = (1.f - g) * pv + g * sn;
        red[tid] = u * u;
    }
    __syncthreads();
    if (tid < Bq) {
        float nn = 0.f;
        int base = tid * 64;
        for (int i = 0; i < 64; ++i) nn += red[base + i];
        float n = sqrtf(nn);
        scale_s[tid] = fminf(1.f, 10.f / fmaxf(n, 1e-6f));
    }
    __syncthreads();
    if (tid < 128) out[tid] = u * scale_s[tid >> 6];
}

// ---------------------------------------------------------------------------
extern "C" void kernel_launch(void* const* d_in, const int* in_sizes, int n_in,
                              void* d_out, int out_size) {
    const float* state = (const float*)d_in[0];
    const float* evk   = (const float*)d_in[1];
    const float* evv   = (const float*)d_in[2];
    const float* Wq    = (const float*)d_in[3];
    const float* Wk    = (const float*)d_in[4];
    const float* Wv    = (const float*)d_in[5];
    const float* gq    = (const float*)d_in[6];
    const float* lq    = (const float*)d_in[7];
    const int*   tok   = (const int*)d_in[8];
    float* out = (float*)d_out;

    k_prep    <<<81, 256>>>(Wk, lq, (const float4*)gq, (const float4*)Wq);
    k_qkh     <<<dim3(4, Gq), 256>>>((const float4*)Wk);
    k_fused   <<<dim3(16, Lq, Bq), 256>>>((const float4*)evk);
    k_comb    <<<Bq, 512>>>();
    k_sh2     <<<dim3(4, Lq, Bq * 2), 256>>>((const float4*)evv);
    k_snew_fin<<<Rq, 256>>>((const float4*)Wv, state, tok, out);
}

// round 14
// speedup vs baseline: 1.2063x; 1.2063x over previous
#include <cuda_runtime.h>
#include <math.h>

// Problem constants (fixed by the dataset)
#define Bq 2
#define Lq 32
#define Eq 256
#define Hq 4096
#define Gq 16
#define Rq 64
#define H4 1024   // Hq/4 (float4 units)

// Scratch (device globals; no allocation in kernel_launch)
__device__ float g_wkq[Hq];            // Wk^T @ layer_query        [H]
__device__ float g_lscore[Bq*Lq];      // layer scores (accum)      [B,L]
__device__ float g_q[Gq*Rq];           // global_q @ Wq^T           [G,R]
__device__ float g_qkh[Gq*Hq];         // inv_sqrt_r * q @ Wk       [G,H]
__device__ float g_scores[Bq*Gq*Eq];   // cross-attn logits (accum) [B,G,E]
__device__ float g_aw[Bq*Eq];          // mean_g attn               [B,E]
__device__ float g_sh[Bq*Hq];          // Σ_{l,e} c*evv (accum)     [B,H]
__device__ float g_snew[Bq*Rq];        // projected new state       [B,R]
__device__ unsigned int g_ctr_wsc;     // last-block counter (k_wsc)
__device__ unsigned int g_ctr_fin;     // last-block counter (k_snew_fin)

// ---------------------------------------------------------------------------
// K1: blocks 0..15  : wkq[h] = Σ_r Wk[r,h]*lq[r]
//     block  16     : zero the atomic accumulators + counters
//     blocks 17..80 : q[g,r] = Σ_h gq[g,h]*Wq[r,h]  (one block per r)
// grid(81) x 256
__global__ void k_prep(const float* __restrict__ Wk, const float* __restrict__ lq,
                       const float4* __restrict__ gq4, const float4* __restrict__ wq4) {
    int tid = threadIdx.x;
    int bx = blockIdx.x;
    if (bx < 16) {
        __shared__ float slq[Rq];
        if (tid < Rq) slq[tid] = lq[tid];
        __syncthreads();
        int h = bx * 256 + tid;
        float s = 0.f;
        #pragma unroll
        for (int r = 0; r < Rq; ++r) s += Wk[r * Hq + h] * slq[r];
        g_wkq[h] = s;
    } else if (bx == 16) {
        if (tid < Bq * Lq) g_lscore[tid] = 0.f;
        for (int i = tid; i < Bq * Hq; i += 256) g_sh[i] = 0.f;
        for (int i = tid; i < Bq * Gq * Eq; i += 256) g_scores[i] = 0.f;
        if (tid == 0) { g_ctr_wsc = 0u; g_ctr_fin = 0u; }
    } else {
        int r = bx - 17;                       // 0..63
        float4 w[4];
        #pragma unroll
        for (int j = 0; j < 4; ++j) w[j] = wq4[r * H4 + j * 256 + tid];
        float p[Gq];
        #pragma unroll
        for (int g = 0; g < Gq; ++g) {
            float s = 0.f;
            #pragma unroll
            for (int j = 0; j < 4; ++j) {
                float4 a = gq4[g * H4 + j * 256 + tid];
                s += a.x * w[j].x + a.y * w[j].y + a.z * w[j].z + a.w * w[j].w;
            }
            p[g] = s;
        }
        __shared__ float sbuf[Gq * 8];
        int lane = tid & 31, warp = tid >> 5;
        #pragma unroll
        for (int g = 0; g < Gq; ++g) {
            float v = p[g];
            #pragma unroll
            for (int o = 16; o; o >>= 1) v += __shfl_down_sync(0xffffffffu, v, o);
            if (lane == 0) sbuf[g * 8 + warp] = v;
        }
        __syncthreads();
        if (tid < Gq) {
            float s = 0.f;
            #pragma unroll
            for (int wgt = 0; wgt < 8; ++wgt) s += sbuf[tid * 8 + wgt];
            g_q[tid * Rq + r] = s;
        }
    }
}

// ---------------------------------------------------------------------------
// K2 (fused):
//   blocks x<16 : layer-score partials Σ_{e,h} evicted_k[b,l,e,h]*wkq[h] (268MB stream)
//   blocks x>=16 (z==0, y<16) : qkh[g,h] = 0.125 * Σ_r q[g,r]*Wk[r,h]  (L2-bound)
// grid(20, L, B) x 256
__global__ void k_main1(const float4* __restrict__ evk4, const float4* __restrict__ wk4) {
    int tid = threadIdx.x;
    if (blockIdx.x < 16) {
        int e0 = blockIdx.x * 16;
        int l  = blockIdx.y;
        int b  = blockIdx.z;
        size_t base4 = ((size_t)((b * Lq + l) * Eq + e0)) * H4;
        const float4* wkq4 = (const float4*)g_wkq;
        float acc = 0.f;
        #pragma unroll 8
        for (int i = 0; i < 64; ++i) {
            int idx = i * 256 + tid;           // 0..16383 (16 rows x 1024 f4)
            float4 d = evk4[base4 + idx];
            float4 w = wkq4[idx & (H4 - 1)];
            acc += d.x * w.x + d.y * w.y + d.z * w.z + d.w * w.w;
        }
        __shared__ float red[256];
        red[tid] = acc; __syncthreads();
        #pragma unroll
        for (int s = 128; s > 0; s >>= 1) {
            if (tid < s) red[tid] += red[tid + s];
            __syncthreads();
        }
        if (tid == 0) atomicAdd(&g_lscore[b * Lq + l], red[0]);
    } else {
        if (blockIdx.z != 0 || blockIdx.y >= 16) return;
        int hc = blockIdx.x - 16;              // 0..3
        int g  = blockIdx.y;                   // 0..15
        __shared__ float sq[Rq];
        if (tid < Rq) sq[tid] = g_q[g * Rq + tid];
        __syncthreads();
        int h4 = hc * 256 + tid;
        float4 v = make_float4(0.f, 0.f, 0.f, 0.f);
        #pragma unroll 16
        for (int r = 0; r < Rq; ++r) {
            float4 w = wk4[r * H4 + h4];
            float qv = sq[r];
            v.x += qv * w.x; v.y += qv * w.y; v.z += qv * w.z; v.w += qv * w.w;
        }
        v.x *= 0.125f; v.y *= 0.125f; v.z *= 0.125f; v.w *= 0.125f;  // inv_sqrt_r
        ((float4*)g_qkh)[g * H4 + h4] = v;
    }
}

// ---------------------------------------------------------------------------
// K3: fused weight+score pass over evicted_k (268 MB, 2nd read):
//   inline softmax(lw) per block; ek_chunk = Σ_l lw*evk (registers only);
//   scores[b,g,e] += Σ_h ek_chunk*qkh[g,h]  (atomicAdd of hc-partials)
//   LAST block (of 2048): softmax over E per (b,g) + aw = mean_g attn.
// grid(4 hc, E, B) x 256
__global__ __launch_bounds__(256) void k_wsc(const float4* __restrict__ evk4) {
    int tid = threadIdx.x;
    int hc = blockIdx.x, e = blockIdx.y, b = blockIdx.z;
    __shared__ float slw[Lq];
    __shared__ float sbuf[Gq * 8];
    __shared__ float abuf[Bq * Gq * Eq];   // 32KB, used only by the last block
    if (tid < 32) {
        float s = g_lscore[b * Lq + tid] * (1.0f / 2048.0f);  // inv_sqrt_r/(temp*E)
        float m = s;
        #pragma unroll
        for (int o = 16; o; o >>= 1) m = fmaxf(m, __shfl_xor_sync(0xffffffffu, m, o));
        float ex = expf(s - m);
        float sum = ex;
        #pragma unroll
        for (int o = 16; o; o >>= 1) sum += __shfl_xor_sync(0xffffffffu, sum, o);
        slw[tid] = ex / sum;
    }
    __syncthreads();
    int off = hc * 256 + tid;                       // f4 offset within H
    const float4* p = evk4 + ((size_t)(b * Lq) * Eq + e) * H4 + off;
    const size_t lstride = (size_t)Eq * H4;
    float4 acc = make_float4(0.f, 0.f, 0.f, 0.f);
    #pragma unroll
    for (int l = 0; l < Lq; ++l) {
        float4 d = p[l * lstride];
        float w = slw[l];
        acc.x += w * d.x; acc.y += w * d.y; acc.z += w * d.z; acc.w += w * d.w;
    }
    // 16 score dots against L2-resident qkh
    const float4* qk4 = (const float4*)g_qkh;
    float sc[Gq];
    #pragma unroll
    for (int g = 0; g < Gq; ++g) {
        float4 q = qk4[g * H4 + off];
        sc[g] = acc.x * q.x + acc.y * q.y + acc.z * q.z + acc.w * q.w;
    }
    int lane = tid & 31, warp = tid >> 5;
    #pragma unroll
    for (int g = 0; g < Gq; ++g) {
        float v = sc[g];
        #pragma unroll
        for (int o = 16; o; o >>= 1) v += __shfl_down_sync(0xffffffffu, v, o);
        if (lane == 0) sbuf[g * 8 + warp] = v;
    }
    __syncthreads();
    if (tid < Gq) {
        float s = 0.f;
        #pragma unroll
        for (int w = 0; w < 8; ++w) s += sbuf[tid * 8 + w];
        atomicAdd(&g_scores[(b * Gq + tid) * Eq + e], s);
    }
    // ---- last-block attention softmax + aw (threadfence + counter) ----
    __syncthreads();
    __shared__ int is_last;
    if (tid == 0) {
        __threadfence();
        is_last = (atomicAdd(&g_ctr_wsc, 1u) == (unsigned)(4 * Eq * Bq - 1)) ? 1 : 0;
    }
    __syncthreads();
    if (!is_last) return;
    __threadfence();
    // 32 (b,g) warp-tasks on 8 warps: softmax each scores row into abuf
    #pragma unroll
    for (int t = 0; t < 4; ++t) {
        int task = warp + t * 8;               // 0..31
        int bb = task >> 4, gg = task & 15;
        float s[8];
        float m = -1e30f;
        #pragma unroll
        for (int j = 0; j < 8; ++j) {
            s[j] = g_scores[(bb * Gq + gg) * Eq + j * 32 + lane];
            m = fmaxf(m, s[j]);
        }
        #pragma unroll
        for (int o = 16; o; o >>= 1) m = fmaxf(m, __shfl_xor_sync(0xffffffffu, m, o));
        float sum = 0.f;
        #pragma unroll
        for (int j = 0; j < 8; ++j) { s[j] = expf(s[j] - m); sum += s[j]; }
        #pragma unroll
        for (int o = 16; o; o >>= 1) sum += __shfl_xor_sync(0xffffffffu, sum, o);
        float inv = 1.0f / sum;
        #pragma unroll
        for (int j = 0; j < 8; ++j)
            abuf[(bb * Gq + gg) * Eq + j * 32 + lane] = s[j] * inv;
    }
    __syncthreads();
    // aw[b,e] = mean_g attn
    #pragma unroll
    for (int bb = 0; bb < Bq; ++bb) {
        float a = 0.f;
        #pragma unroll
        for (int gg = 0; gg < Gq; ++gg) a += abuf[(bb * Gq + gg) * Eq + tid];
        g_aw[bb * Eq + tid] = a * (1.0f / (float)Gq);
    }
}

// ---------------------------------------------------------------------------
// K4: sh[b,h] += Σ_{l,e} (lw[b,l]*aw[b,e]) * evv[b,l,e,h]  (268 MB, read ONCE)
// grid(4 hc, L, B*2 e-halves) x 256; inline lw softmax.
__global__ void k_sh2(const float4* __restrict__ evv4) {
    __shared__ float sca[128];
    __shared__ float slw_s;
    int tid = threadIdx.x;
    int hc = blockIdx.x, l = blockIdx.y;
    int b = blockIdx.z & 1, eh = blockIdx.z >> 1;
    if (tid < 32) {
        float s = g_lscore[b * Lq + tid] * (1.0f / 2048.0f);
        float m = s;
        #pragma unroll
        for (int o = 16; o; o >>= 1) m = fmaxf(m, __shfl_xor_sync(0xffffffffu, m, o));
        float ex = expf(s - m);
        float sum = ex;
        #pragma unroll
        for (int o = 16; o; o >>= 1) sum += __shfl_xor_sync(0xffffffffu, sum, o);
        if (tid == l) slw_s = ex / sum;
    }
    __syncthreads();
    if (tid < 128) sca[tid] = g_aw[b * Eq + eh * 128 + tid] * slw_s;
    __syncthreads();
    const float4* base = evv4 + ((size_t)((b * Lq + l) * Eq + eh * 128)) * H4
                       + hc * 256 + tid;
    float4 acc = make_float4(0.f, 0.f, 0.f, 0.f);
    #pragma unroll 4
    for (int e = 0; e < 128; ++e) {
        float4 d = base[(size_t)e * H4];
        float c = sca[e];
        acc.x += c * d.x; acc.y += c * d.y; acc.z += c * d.z; acc.w += c * d.w;
    }
    float* shp = &g_sh[b * Hq + (hc * 256 + tid) * 4];
    atomicAdd(shp + 0, acc.x);
    atomicAdd(shp + 1, acc.y);
    atomicAdd(shp + 2, acc.z);
    atomicAdd(shp + 3, acc.w);
}

// ---------------------------------------------------------------------------
// K5: s_new[b,r] = Σ_h sh[b,h]*Wv[r,h] (one block per r, Wv read once),
// then the LAST block performs the gated update + norm clamp (fused fin).
// grid(64) x 256.
__global__ void k_snew_fin(const float4* __restrict__ wv4,
                           const float* __restrict__ state,
                           const int* __restrict__ tok,
                           float* __restrict__ out) {
    int tid = threadIdx.x;
    int r = blockIdx.x;
    const float4* sh4 = (const float4*)g_sh;
    float4 w[4];
    #pragma unroll
    for (int j = 0; j < 4; ++j) w[j] = wv4[r * H4 + j * 256 + tid];
    float p[Bq];
    #pragma unroll
    for (int b = 0; b < Bq; ++b) {
        float s = 0.f;
        #pragma unroll
        for (int j = 0; j < 4; ++j) {
            float4 a = sh4[b * H4 + j * 256 + tid];
            s += a.x * w[j].x + a.y * w[j].y + a.z * w[j].z + a.w * w[j].w;
        }
        p[b] = s;
    }
    __shared__ float sbuf[Bq * 8];
    int lane = tid & 31, warp = tid >> 5;
    #pragma unroll
    for (int b = 0; b < Bq; ++b) {
        float v = p[b];
        #pragma unroll
        for (int o = 16; o; o >>= 1) v += __shfl_down_sync(0xffffffffu, v, o);
        if (lane == 0) sbuf[b * 8 + warp] = v;
    }
    __syncthreads();
    if (tid < Bq) {
        float s = 0.f;
        #pragma unroll
        for (int wgt = 0; wgt < 8; ++wgt) s += sbuf[tid * 8 + wgt];
        g_snew[tid * Rq + r] = s;
    }
    // ---- last-block finalization (threadfence + counter) ----
    __syncthreads();
    __shared__ int is_last;
    if (tid == 0) {
        __threadfence();
        is_last = (atomicAdd(&g_ctr_fin, 1u) == (unsigned)(Rq - 1)) ? 1 : 0;
    }
    __syncthreads();
    if (!is_last) return;
    __threadfence();

    __shared__ float red[3 * 128];
    __shared__ float gate_s[Bq], scale_s[Bq];
    float pv = 0.f, sn = 0.f;
    if (tid < 128) {
        pv = state[tid];
        sn = g_snew[tid];
        red[tid] = pv * pv; red[128 + tid] = sn * sn; red[256 + tid] = pv * sn;
    }
    __syncthreads();
    if (tid < Bq) {
        float pp = 0.f, ss = 0.f, ps = 0.f;
        int base = tid * 64;
        for (int i = 0; i < 64; ++i) {
            pp += red[base + i]; ss += red[128 + base + i]; ps += red[256 + base + i];
        }
        float np = fmaxf(sqrtf(pp), 1e-6f);
        float ns = fmaxf(sqrtf(ss), 1e-6f);
        float sim = ps / (np * ns);
        sim = fminf(1.f, fmaxf(-1.f, sim));
        float gate = 0.1f + 0.8f * 0.5f * (sim + 1.f);
        float evd = fminf(1.f, (float)tok[0] * (1.0f / 256.0f));
        gate_s[tid] = gate * evd;
    }
    __syncthreads();
    float u = 0.f;
    if (tid < 128) {
        float g = gate_s[tid >> 6];
        u = (1.f - g) * pv + g * sn;
        red[tid] = u * u;
    }
    __syncthreads();
    if (tid < Bq) {
        float nn = 0.f;
        int base = tid * 64;
        for (int i = 0; i < 64; ++i) nn += red[base + i];
        float n = sqrtf(nn);
        scale_s[tid] = fminf(1.f, 10.f / fmaxf(n, 1e-6f));
    }
    __syncthreads();
    if (tid < 128) out[tid] = u * scale_s[tid >> 6];
}

// ---------------------------------------------------------------------------
extern "C" void kernel_launch(void* const* d_in, const int* in_sizes, int n_in,
                              void* d_out, int out_size) {
    const float* state = (const float*)d_in[0];
    const float* evk   = (const float*)d_in[1];
    const float* evv   = (const float*)d_in[2];
    const float* Wq    = (const float*)d_in[3];
    const float* Wk    = (const float*)d_in[4];
    const float* Wv    = (const float*)d_in[5];
    const float* gq    = (const float*)d_in[6];
    const float* lq    = (const float*)d_in[7];
    const int*   tok   = (const int*)d_in[8];
    float* out = (float*)d_out;

    k_prep    <<<81, 256>>>(Wk, lq, (const float4*)gq, (const float4*)Wq);
    k_main1   <<<dim3(20, Lq, Bq), 256>>>((const float4*)evk, (const float4*)Wk);
    k_wsc     <<<dim3(4, Eq, Bq), 256>>>((const float4*)evk);
    k_sh2     <<<dim3(4, Lq, Bq * 2), 256>>>((const float4*)evv);
    k_snew_fin<<<Rq, 256>>>((const float4*)Wv, state, tok, out);
}